// round 17
// baseline (speedup 1.0000x reference)
#include <cuda_runtime.h>
#include <cuda_bf16.h>
#include <cuda_fp16.h>
#include <math.h>
#include <stdint.h>

// ---------------- problem constants ----------------
#define BATCH   32
#define IMG_H   56
#define IMG_W   56
#define CH      256
#define WS      7
#define SHIFT_  3
#define HEADS   8
#define HD      32
#define HIDDEN  1024
#define NTOK    49
#define T_TOK   (BATCH*IMG_H*IMG_W)   // 100352

typedef __nv_bfloat16 bf16;
typedef __nv_bfloat162 bf162;

// ---------------- scratch ----------------
__device__ bf16  g_xw [(size_t)T_TOK * CH];
__device__ bf16  g_qkv[(size_t)T_TOK * 3 * CH];
__device__ float g_y  [(size_t)T_TOK * CH];
__device__ bf16  g_z  [(size_t)T_TOK * CH];
__device__ bf16  g_m1 [(size_t)T_TOK * HIDDEN];
__device__ bf16  g_wq [256 * 768];
__device__ bf16  g_wp [256 * 256];
__device__ bf16  g_w1 [256 * 1024];
__device__ bf16  g_w2 [1024 * 256];

__device__ __forceinline__ int map_token(int r) {
    int w = r / NTOK, n = r - w * NTOK;
    int b = w >> 6, widx = w & 63;
    int wh = widx >> 3, ww = widx & 7;
    int i = n / WS, j = n - i * WS;
    int h = wh * WS + i + SHIFT_;  if (h >= IMG_H) h -= IMG_H;
    int v = ww * WS + j + SHIFT_;  if (v >= IMG_W) v -= IMG_W;
    return (b * IMG_H + h) * IMG_W + v;
}

__device__ __forceinline__ void mma_bf16(float* c, const uint32_t* a, const uint32_t* b) {
    asm volatile(
        "mma.sync.aligned.m16n8k16.row.col.f32.bf16.bf16.f32 "
        "{%0,%1,%2,%3}, {%4,%5,%6,%7}, {%8,%9}, {%0,%1,%2,%3};\n"
        : "+f"(c[0]), "+f"(c[1]), "+f"(c[2]), "+f"(c[3])
        : "r"(a[0]), "r"(a[1]), "r"(a[2]), "r"(a[3]), "r"(b[0]), "r"(b[1]));
}
__device__ __forceinline__ void mma_f16(float* c, const uint32_t* a, const uint32_t* b) {
    asm volatile(
        "mma.sync.aligned.m16n8k16.row.col.f32.f16.f16.f32 "
        "{%0,%1,%2,%3}, {%4,%5,%6,%7}, {%8,%9}, {%0,%1,%2,%3};\n"
        : "+f"(c[0]), "+f"(c[1]), "+f"(c[2]), "+f"(c[3])
        : "r"(a[0]), "r"(a[1]), "r"(a[2]), "r"(a[3]), "r"(b[0]), "r"(b[1]));
}
__device__ __forceinline__ void ldm_x4(uint32_t& r0, uint32_t& r1, uint32_t& r2, uint32_t& r3, uint32_t a) {
    asm volatile("ldmatrix.sync.aligned.m8n8.x4.shared.b16 {%0,%1,%2,%3}, [%4];"
                 : "=r"(r0), "=r"(r1), "=r"(r2), "=r"(r3) : "r"(a));
}
__device__ __forceinline__ void ldm_x4t(uint32_t& r0, uint32_t& r1, uint32_t& r2, uint32_t& r3, uint32_t a) {
    asm volatile("ldmatrix.sync.aligned.m8n8.x4.trans.shared.b16 {%0,%1,%2,%3}, [%4];"
                 : "=r"(r0), "=r"(r1), "=r"(r2), "=r"(r3) : "r"(a));
}
__device__ __forceinline__ void cp16(uint32_t smem_addr, const void* gptr) {
    asm volatile("cp.async.cg.shared.global [%0], [%1], 16;\n" :: "r"(smem_addr), "l"(gptr));
}
__device__ __forceinline__ void cp_commit() { asm volatile("cp.async.commit_group;\n"); }
__device__ __forceinline__ void cp_wait0()  { asm volatile("cp.async.wait_group 0;\n"); }
__device__ __forceinline__ void cp_wait1()  { asm volatile("cp.async.wait_group 1;\n"); }

__device__ __forceinline__ uint32_t pack_h2(float x, float y) {
    __half2 h = __float22half2_rn(make_float2(x, y));
    return *(uint32_t*)&h;
}

// ---------------- fused weight conversion ----------------
#define NW0 (256*768)
#define NW1 (256*256)
#define NW2 (256*1024)
#define NW3 (1024*256)
__global__ void __launch_bounds__(256) conv_all(const float* __restrict__ i0, const float* __restrict__ i1,
                                                const float* __restrict__ i2, const float* __restrict__ i3,
                                                bf16* __restrict__ o0, bf16* __restrict__ o1,
                                                bf16* __restrict__ o2, bf16* __restrict__ o3) {
    int i = (blockIdx.x * blockDim.x + threadIdx.x) * 2;
    const float* in; bf16* out; int off;
    if (i < NW0)                       { in = i0; out = o0; off = i; }
    else if (i < NW0 + NW1)            { in = i1; out = o1; off = i - NW0; }
    else if (i < NW0 + NW1 + NW2)      { in = i2; out = o2; off = i - NW0 - NW1; }
    else if (i < NW0 + NW1 + NW2 + NW3){ in = i3; out = o3; off = i - NW0 - NW1 - NW2; }
    else return;
    float2 f = *(const float2*)(in + off);
    *(bf162*)(out + off) = __floats2bfloat162_rn(f.x, f.y);
}

// ---------------- LayerNorm1 (+roll+partition) -> bf16 ----------------
__global__ void __launch_bounds__(256) ln1_kernel(const float* __restrict__ in,
                                                  const float* __restrict__ gam,
                                                  const float* __restrict__ bet,
                                                  bf16* __restrict__ out) {
    int warp = (blockIdx.x * blockDim.x + threadIdx.x) >> 5;
    int lane = threadIdx.x & 31;
    if (warp >= T_TOK) return;
    int src = map_token(warp);

    const float4* row = (const float4*)(in + (size_t)src * CH);
    float4 a = row[lane];
    float4 b = row[lane + 32];

    float s = a.x + a.y + a.z + a.w + b.x + b.y + b.z + b.w;
    #pragma unroll
    for (int o = 16; o; o >>= 1) s += __shfl_xor_sync(0xffffffffu, s, o);
    float mu = s * (1.0f / CH);

    float vs = 0.f, d;
    d = a.x - mu; vs += d * d;  d = a.y - mu; vs += d * d;
    d = a.z - mu; vs += d * d;  d = a.w - mu; vs += d * d;
    d = b.x - mu; vs += d * d;  d = b.y - mu; vs += d * d;
    d = b.z - mu; vs += d * d;  d = b.w - mu; vs += d * d;
    #pragma unroll
    for (int o = 16; o; o >>= 1) vs += __shfl_xor_sync(0xffffffffu, vs, o);
    float inv = rsqrtf(vs * (1.0f / CH) + 1e-5f);

    float4 g0 = ((const float4*)gam)[lane], g1 = ((const float4*)gam)[lane + 32];
    float4 b0 = ((const float4*)bet)[lane], b1 = ((const float4*)bet)[lane + 32];

    bf162* orow = (bf162*)(out + (size_t)warp * CH);
    orow[2 * lane]          = __floats2bfloat162_rn((a.x - mu) * inv * g0.x + b0.x, (a.y - mu) * inv * g0.y + b0.y);
    orow[2 * lane + 1]      = __floats2bfloat162_rn((a.z - mu) * inv * g0.z + b0.z, (a.w - mu) * inv * g0.w + b0.w);
    orow[64 + 2 * lane]     = __floats2bfloat162_rn((b.x - mu) * inv * g1.x + b1.x, (b.y - mu) * inv * g1.y + b1.y);
    orow[64 + 2 * lane + 1] = __floats2bfloat162_rn((b.z - mu) * inv * g1.z + b1.z, (b.w - mu) * inv * g1.w + b1.w);
}

// ---------------- bf16 GEMM 256x128x32, 8 warps, warp tile 64x64 ----------------
//   EPI 0: +bias -> bf16      EPI 2: gelu(+bias)->bf16   EPI 3: +extra +bias -> fp32
#define ASTRIDE 40
#define BSTRIDE 136
#define A_STAGE_B (256 * ASTRIDE * 2)   // 20480
#define B_STAGE_B (32 * BSTRIDE * 2)    // 8704
#define SMEM_GEMM (3 * (A_STAGE_B + B_STAGE_B))   // 87552

template<int EPI>
__global__ void __launch_bounds__(256) mma_gemm(const bf16* __restrict__ A,
                                                const bf16* __restrict__ Bw,
                                                const float* __restrict__ bias,
                                                float* __restrict__ Cout,
                                                int Ndim, int Kdim,
                                                const float* __restrict__ extra) {
    extern __shared__ char smem[];
    bf16* As = (bf16*)smem;                       // [3][256][ASTRIDE]
    bf16* Bs = (bf16*)(smem + 3 * A_STAGE_B);     // [3][32][BSTRIDE]

    const int tid  = threadIdx.x;
    const int brow = blockIdx.y * 256;
    const int bcol = blockIdx.x * 128;
    const int warp = tid >> 5, lane = tid & 31;
    const int wm = (warp & 3) * 64, wn = (warp >> 2) * 64;
    const int lk = lane & 3, lr = lane >> 2;

    const int bk = tid >> 3, bc = (tid & 7) * 16;
    const bf16* Ap = A  + (size_t)(brow + tid) * Kdim;
    const bf16* Bp = Bw + (size_t)bk * Ndim + bcol + bc;

    const uint32_t sAb = (uint32_t)__cvta_generic_to_shared(As + tid * ASTRIDE);
    const uint32_t sBb = (uint32_t)__cvta_generic_to_shared(Bs + bk * BSTRIDE + bc);

    const int lrow = lane & 15, lsel = lane >> 4;
    uint32_t laA[4], laB[4];
    #pragma unroll
    for (int mi = 0; mi < 4; mi++)
        laA[mi] = (uint32_t)__cvta_generic_to_shared(As + (wm + mi * 16 + lrow) * ASTRIDE + lsel * 8);
    #pragma unroll
    for (int p = 0; p < 4; p++)
        laB[p] = (uint32_t)__cvta_generic_to_shared(Bs + lrow * BSTRIDE + wn + p * 16 + lsel * 8);

    float acc[4][8][4];
    #pragma unroll
    for (int i = 0; i < 4; i++)
        #pragma unroll
        for (int j = 0; j < 8; j++)
            #pragma unroll
            for (int q = 0; q < 4; q++) acc[i][j][q] = 0.f;

    const int ktiles = Kdim >> 5;

    #pragma unroll
    for (int t = 0; t < 2; t++) {
        const bf16* Ap2 = Ap + t * 32;
        const bf16* Bp2 = Bp + (size_t)t * 32 * Ndim;
        uint32_t aA = sAb + t * A_STAGE_B, aB = sBb + t * B_STAGE_B;
        cp16(aA, Ap2);          cp16(aA + 16, Ap2 + 8);
        cp16(aA + 32, Ap2 + 16); cp16(aA + 48, Ap2 + 24);
        cp16(aB, Bp2);          cp16(aB + 16, Bp2 + 8);
        cp_commit();
    }

    int cs = 0;
    for (int kt = 0; kt < ktiles; kt++) {
        if (kt + 1 < ktiles) cp_wait1(); else cp_wait0();
        __syncthreads();

        if (kt + 2 < ktiles) {
            int ps = cs + 2; if (ps >= 3) ps -= 3;
            const bf16* Ap2 = Ap + (kt + 2) * 32;
            const bf16* Bp2 = Bp + (size_t)(kt + 2) * 32 * Ndim;
            uint32_t aA = sAb + ps * A_STAGE_B, aB = sBb + ps * B_STAGE_B;
            cp16(aA, Ap2);           cp16(aA + 16, Ap2 + 8);
            cp16(aA + 32, Ap2 + 16); cp16(aA + 48, Ap2 + 24);
            cp16(aB, Bp2);           cp16(aB + 16, Bp2 + 8);
            cp_commit();
        }

        const uint32_t offA = cs * A_STAGE_B, offB = cs * B_STAGE_B;
        #pragma unroll
        for (int ks = 0; ks < 2; ks++) {
            uint32_t af[4][4], bfr[8][2];
            #pragma unroll
            for (int mi = 0; mi < 4; mi++)
                ldm_x4(af[mi][0], af[mi][1], af[mi][2], af[mi][3], laA[mi] + offA + ks * 32);
            #pragma unroll
            for (int p = 0; p < 4; p++)
                ldm_x4t(bfr[2 * p][0], bfr[2 * p][1], bfr[2 * p + 1][0], bfr[2 * p + 1][1],
                        laB[p] + offB + ks * 16 * (BSTRIDE * 2));
            #pragma unroll
            for (int mi = 0; mi < 4; mi++)
                #pragma unroll
                for (int ni = 0; ni < 8; ni++)
                    mma_bf16(acc[mi][ni], af[mi], bfr[ni]);
        }
        cs = (cs == 2) ? 0 : cs + 1;
    }

    #pragma unroll
    for (int mi = 0; mi < 4; mi++) {
        int r0 = brow + wm + mi * 16 + lr;
        int r1 = r0 + 8;
        #pragma unroll
        for (int ni = 0; ni < 8; ni++) {
            int col = bcol + wn + ni * 8 + 2 * lk;
            float2 bs = *(const float2*)(bias + col);
            float v0 = acc[mi][ni][0] + bs.x, v1 = acc[mi][ni][1] + bs.y;
            float v2 = acc[mi][ni][2] + bs.x, v3 = acc[mi][ni][3] + bs.y;
            if (EPI == 0) {
                bf162* Co = (bf162*)Cout;
                Co[((size_t)r0 * Ndim + col) >> 1] = __floats2bfloat162_rn(v0, v1);
                Co[((size_t)r1 * Ndim + col) >> 1] = __floats2bfloat162_rn(v2, v3);
            } else if (EPI == 2) {
                const float r2i = 0.70710678118654752f;
                v0 = 0.5f * v0 * (1.0f + erff(v0 * r2i));
                v1 = 0.5f * v1 * (1.0f + erff(v1 * r2i));
                v2 = 0.5f * v2 * (1.0f + erff(v2 * r2i));
                v3 = 0.5f * v3 * (1.0f + erff(v3 * r2i));
                bf162* Co = (bf162*)Cout;
                Co[((size_t)r0 * Ndim + col) >> 1] = __floats2bfloat162_rn(v0, v1);
                Co[((size_t)r1 * Ndim + col) >> 1] = __floats2bfloat162_rn(v2, v3);
            } else {
                float2 e0 = *(const float2*)(extra + (size_t)r0 * CH + col);
                float2 e1 = *(const float2*)(extra + (size_t)r1 * CH + col);
                *(float2*)(Cout + (size_t)r0 * CH + col) = make_float2(e0.x + v0, e0.y + v1);
                *(float2*)(Cout + (size_t)r1 * CH + col) = make_float2(e1.x + v2, e1.y + v3);
            }
        }
    }
}

// ---------------- proj GEMM 128x256x32 + shortcut + fused LN2 ----------------
// A [M][256] bf16 (attn out, window order); Bw = wp [256][256] bf16.
// y[t] = x[t] + A@W + b (fp32, scatter); z[t] = LN(y row) bf16 (scatter).
#define PA_STAGE (128 * ASTRIDE * 2)          // 10240
#define PB_STAGE (32 * BSTRIDE * 2)           // 8704 per half
#define PROJ_STAGE (PA_STAGE + 2 * PB_STAGE)  // 27648
#define SMEM_PROJ (3 * PROJ_STAGE)            // 82944

__global__ void __launch_bounds__(256) proj_ln_gemm(const bf16* __restrict__ A,
                                                    const bf16* __restrict__ Bw,
                                                    const float* __restrict__ bias,
                                                    const float* __restrict__ x,
                                                    float* __restrict__ y,
                                                    const float* __restrict__ gam,
                                                    const float* __restrict__ bet,
                                                    bf16* __restrict__ z) {
    extern __shared__ char smem[];
    bf16* As  = (bf16*)smem;                                   // [3][128][40]
    bf16* Bs0 = (bf16*)(smem + 3 * PA_STAGE);                  // [3][32][136]
    bf16* Bs1 = (bf16*)(smem + 3 * PA_STAGE + 3 * PB_STAGE);   // [3][32][136]

    const int tid  = threadIdx.x;
    const int brow = blockIdx.x * 128;
    const int warp = tid >> 5, lane = tid & 31;
    const int wmid = warp & 1, wnid = warp >> 1;
    const int wm = wmid * 64;
    const int wn = wnid * 64;
    const int lk = lane & 3, lr = lane >> 2;

    // loaders
    const int arow = tid >> 1, ac = (tid & 1) * 16;
    const bf16* Ap = A + (size_t)(brow + arow) * 256 + ac;
    const uint32_t sAb = (uint32_t)__cvta_generic_to_shared(As + arow * ASTRIDE + ac);

    const int bk = tid >> 3, bc = (tid & 7) * 32;
    const int bhi = (bc >= 128), bcl = bhi ? bc - 128 : bc;
    const bf16* Bp = Bw + (size_t)bk * 256 + bc;
    const uint32_t sBb = (uint32_t)__cvta_generic_to_shared(
        (bhi ? Bs1 : Bs0) + bk * BSTRIDE + bcl);

    const int lrow = lane & 15, lsel = lane >> 4;
    uint32_t laA[4], laB[4];
    #pragma unroll
    for (int mi = 0; mi < 4; mi++)
        laA[mi] = (uint32_t)__cvta_generic_to_shared(As + (wm + mi * 16 + lrow) * ASTRIDE + lsel * 8);
    {
        bf16* Bx = (wnid < 2) ? Bs0 : Bs1;
        int wn_lo = (wnid & 1) * 64;
        #pragma unroll
        for (int p = 0; p < 4; p++)
            laB[p] = (uint32_t)__cvta_generic_to_shared(Bx + lrow * BSTRIDE + wn_lo + p * 16 + lsel * 8);
    }

    float acc[4][8][4];
    #pragma unroll
    for (int i = 0; i < 4; i++)
        #pragma unroll
        for (int j = 0; j < 8; j++)
            #pragma unroll
            for (int q = 0; q < 4; q++) acc[i][j][q] = 0.f;

    const int ktiles = 8;  // K=256

    #pragma unroll
    for (int t = 0; t < 2; t++) {
        const bf16* Ap2 = Ap + t * 32;
        const bf16* Bp2 = Bp + (size_t)t * 32 * 256;
        uint32_t aA = sAb + t * PA_STAGE, aB = sBb + t * PB_STAGE;
        cp16(aA, Ap2);  cp16(aA + 16, Ap2 + 8);
        cp16(aB, Bp2);  cp16(aB + 16, Bp2 + 8);
        cp16(aB + 32, Bp2 + 16);  cp16(aB + 48, Bp2 + 24);
        cp_commit();
    }

    int cs = 0;
    for (int kt = 0; kt < ktiles; kt++) {
        if (kt + 1 < ktiles) cp_wait1(); else cp_wait0();
        __syncthreads();

        if (kt + 2 < ktiles) {
            int ps = cs + 2; if (ps >= 3) ps -= 3;
            const bf16* Ap2 = Ap + (kt + 2) * 32;
            const bf16* Bp2 = Bp + (size_t)(kt + 2) * 32 * 256;
            uint32_t aA = sAb + ps * PA_STAGE, aB = sBb + ps * PB_STAGE;
            cp16(aA, Ap2);  cp16(aA + 16, Ap2 + 8);
            cp16(aB, Bp2);  cp16(aB + 16, Bp2 + 8);
            cp16(aB + 32, Bp2 + 16);  cp16(aB + 48, Bp2 + 24);
            cp_commit();
        }

        const uint32_t offA = cs * PA_STAGE, offB = cs * PB_STAGE;
        #pragma unroll
        for (int ks = 0; ks < 2; ks++) {
            uint32_t af[4][4], bfr[8][2];
            #pragma unroll
            for (int mi = 0; mi < 4; mi++)
                ldm_x4(af[mi][0], af[mi][1], af[mi][2], af[mi][3], laA[mi] + offA + ks * 32);
            #pragma unroll
            for (int p = 0; p < 4; p++)
                ldm_x4t(bfr[2 * p][0], bfr[2 * p][1], bfr[2 * p + 1][0], bfr[2 * p + 1][1],
                        laB[p] + offB + ks * 16 * (BSTRIDE * 2));
            #pragma unroll
            for (int mi = 0; mi < 4; mi++)
                #pragma unroll
                for (int ni = 0; ni < 8; ni++)
                    mma_bf16(acc[mi][ni], af[mi], bfr[ni]);
        }
        cs = (cs == 2) ? 0 : cs + 1;
    }

    // ---- epilogue: y = x + proj + b; fused LN2 -> z ----
    __syncthreads();                 // done with smem stages
    float* red = (float*)smem;       // [128][8]: sums [0..3]=sum per wnid, [4..7]=sumsq

    int tok0[4], tok1[4];
    #pragma unroll
    for (int mi = 0; mi < 4; mi++) {
        const int rl0 = wm + mi * 16 + lr, rl1 = rl0 + 8;
        const int t0 = map_token(brow + rl0), t1 = map_token(brow + rl1);
        tok0[mi] = t0; tok1[mi] = t1;
        float s0 = 0.f, q0 = 0.f, s1 = 0.f, q1 = 0.f;
        #pragma unroll
        for (int ni = 0; ni < 8; ni++) {
            int col = wn + ni * 8 + 2 * lk;
            float2 bs = *(const float2*)(bias + col);
            float2 e0 = *(const float2*)(x + (size_t)t0 * CH + col);
            float2 e1 = *(const float2*)(x + (size_t)t1 * CH + col);
            float v0 = acc[mi][ni][0] + bs.x + e0.x;
            float v1 = acc[mi][ni][1] + bs.y + e0.y;
            float v2 = acc[mi][ni][2] + bs.x + e1.x;
            float v3 = acc[mi][ni][3] + bs.y + e1.y;
            acc[mi][ni][0] = v0; acc[mi][ni][1] = v1;
            acc[mi][ni][2] = v2; acc[mi][ni][3] = v3;
            *(float2*)(y + (size_t)t0 * CH + col) = make_float2(v0, v1);
            *(float2*)(y + (size_t)t1 * CH + col) = make_float2(v2, v3);
            s0 += v0 + v1;  q0 += v0 * v0 + v1 * v1;
            s1 += v2 + v3;  q1 += v2 * v2 + v3 * v3;
        }
        s0 += __shfl_xor_sync(0xffffffffu, s0, 1); s0 += __shfl_xor_sync(0xffffffffu, s0, 2);
        q0 += __shfl_xor_sync(0xffffffffu, q0, 1); q0 += __shfl_xor_sync(0xffffffffu, q0, 2);
        s1 += __shfl_xor_sync(0xffffffffu, s1, 1); s1 += __shfl_xor_sync(0xffffffffu, s1, 2);
        q1 += __shfl_xor_sync(0xffffffffu, q1, 1); q1 += __shfl_xor_sync(0xffffffffu, q1, 2);
        if (lk == 0) {
            red[rl0 * 8 + wnid]     = s0;  red[rl0 * 8 + 4 + wnid] = q0;
            red[rl1 * 8 + wnid]     = s1;  red[rl1 * 8 + 4 + wnid] = q1;
        }
    }
    __syncthreads();

    #pragma unroll
    for (int mi = 0; mi < 4; mi++) {
        const int rl0 = wm + mi * 16 + lr, rl1 = rl0 + 8;
        const int t0 = tok0[mi], t1 = tok1[mi];
        float s0 = red[rl0 * 8 + 0] + red[rl0 * 8 + 1] + red[rl0 * 8 + 2] + red[rl0 * 8 + 3];
        float q0 = red[rl0 * 8 + 4] + red[rl0 * 8 + 5] + red[rl0 * 8 + 6] + red[rl0 * 8 + 7];
        float s1 = red[rl1 * 8 + 0] + red[rl1 * 8 + 1] + red[rl1 * 8 + 2] + red[rl1 * 8 + 3];
        float q1 = red[rl1 * 8 + 4] + red[rl1 * 8 + 5] + red[rl1 * 8 + 6] + red[rl1 * 8 + 7];
        float mu0 = s0 * (1.0f / CH), mu1 = s1 * (1.0f / CH);
        float inv0 = rsqrtf(q0 * (1.0f / CH) - mu0 * mu0 + 1e-5f);
        float inv1 = rsqrtf(q1 * (1.0f / CH) - mu1 * mu1 + 1e-5f);
        #pragma unroll
        for (int ni = 0; ni < 8; ni++) {
            int col = wn + ni * 8 + 2 * lk;
            float2 g = *(const float2*)(gam + col);
            float2 b = *(const float2*)(bet + col);
            *(bf162*)(z + (size_t)t0 * CH + col) = __floats2bfloat162_rn(
                (acc[mi][ni][0] - mu0) * inv0 * g.x + b.x,
                (acc[mi][ni][1] - mu0) * inv0 * g.y + b.y);
            *(bf162*)(z + (size_t)t1 * CH + col) = __floats2bfloat162_rn(
                (acc[mi][ni][2] - mu1) * inv1 * g.x + b.x,
                (acc[mi][ni][3] - mu1) * inv1 * g.y + b.y);
        }
    }
}

// ---------------- tensor-core attention ----------------
__global__ void __launch_bounds__(128) attn_kernel(const bf16* __restrict__ qkv,
                                                   const float* __restrict__ rel_bias,
                                                   bf16* __restrict__ out) {
    __shared__ bf16   qs[64][40];
    __shared__ bf16   ks[64][40];
    __shared__ __half vs[64][40];
    __shared__ float  sbias[169];
    __shared__ __align__(8) int sinfo[64];

    const int blk = blockIdx.x;
    const int w = blk >> 3, hh = blk & 7;
    const int tid = threadIdx.x;
    const int warp = tid >> 5, lane = tid & 31;
    const int lr = lane >> 2, lk = lane & 3;
    const int lrow = lane & 15, lsel = lane >> 4;
    const int wm = warp * 16;
    const float scale = 0.17677669529663687f;

    for (int idx = tid; idx < 15 * 40; idx += 128) {
        int r = 49 + idx / 40, cc = idx - (idx / 40) * 40;
        qs[r][cc] = __float2bfloat16(0.f);
        ks[r][cc] = __float2bfloat16(0.f);
        vs[r][cc] = __float2half(0.f);
    }
    for (int idx = tid; idx < 49 * 4; idx += 128) {
        int n = idx >> 2, c8 = (idx & 3) * 8;
        const bf16* base = qkv + (size_t)(w * 49 + n) * (3 * CH) + hh * 32 + c8;
        *(uint4*)&qs[n][c8] = *(const uint4*)(base);
        *(uint4*)&ks[n][c8] = *(const uint4*)(base + CH);
        uint4 vv = *(const uint4*)(base + 2 * CH);
        bf162* vp = (bf162*)&vv;
        __half2 hv[4];
        #pragma unroll
        for (int t = 0; t < 4; t++) hv[t] = __float22half2_rn(__bfloat1622float2(vp[t]));
        *(uint4*)&vs[n][c8] = *(uint4*)hv;
    }
    for (int i = tid; i < 169; i += 128) sbias[i] = rel_bias[i * 8 + hh];
    if (tid < 64) {
        int c = tid, info;
        if (c < 49) {
            int i = (c * 37) >> 8, j = c - 7 * i;
            int wh = (w & 63) >> 3, ww = w & 7;
            int hn = wh * 7 + i, wn = ww * 7 + j;
            int tag = (hn < 49 ? 0 : (hn < 53 ? 1 : 2)) * 3 + (wn < 49 ? 0 : (wn < 53 ? 1 : 2));
            info = (tag << 8) | (i * 13 + j);
        } else info = (15 << 8);
        sinfo[c] = info;
    }
    __syncthreads();

    float c[8][4];
    #pragma unroll
    for (int j = 0; j < 8; j++)
        #pragma unroll
        for (int q = 0; q < 4; q++) c[j][q] = 0.f;

    const uint32_t laQ = (uint32_t)__cvta_generic_to_shared(&qs[wm + lrow][lsel * 8]);
    uint32_t laK[4];
    #pragma unroll
    for (int np = 0; np < 4; np++)
        laK[np] = (uint32_t)__cvta_generic_to_shared(&ks[np * 16 + lrow][lsel * 8]);

    #pragma unroll
    for (int kh = 0; kh < 2; kh++) {
        uint32_t a[4];
        ldm_x4(a[0], a[1], a[2], a[3], laQ + kh * 32);
        #pragma unroll
        for (int np = 0; np < 4; np++) {
            uint32_t r0, r1, r2, r3;
            ldm_x4(r0, r1, r2, r3, laK[np] + kh * 32);
            uint32_t bl[2] = {r0, r2}, bu[2] = {r1, r3};
            mma_bf16(c[2 * np],     a, bl);
            mma_bf16(c[2 * np + 1], a, bu);
        }
    }

    const int ri0 = sinfo[wm + lr], ri1 = sinfo[wm + lr + 8];
    const int rv0 = ri0 & 255, rt0 = ri0 >> 8;
    const int rv1 = ri1 & 255, rt1 = ri1 >> 8;
    float mx0 = -1e30f, mx1 = -1e30f;
    #pragma unroll
    for (int j = 0; j < 8; j++) {
        int2 ci = *(const int2*)&sinfo[j * 8 + 2 * lk];
        int cv0 = ci.x & 255, ct0 = ci.x >> 8;
        int cv1 = ci.y & 255, ct1 = ci.y >> 8;
        c[j][0] = c[j][0] * scale + sbias[cv0 - rv0 + 84] + (ct0 != rt0 ? -100.f : 0.f);
        c[j][1] = c[j][1] * scale + sbias[cv1 - rv0 + 84] + (ct1 != rt0 ? -100.f : 0.f);
        c[j][2] = c[j][2] * scale + sbias[cv0 - rv1 + 84] + (ct0 != rt1 ? -100.f : 0.f);
        c[j][3] = c[j][3] * scale + sbias[cv1 - rv1 + 84] + (ct1 != rt1 ? -100.f : 0.f);
        mx0 = fmaxf(mx0, fmaxf(c[j][0], c[j][1]));
        mx1 = fmaxf(mx1, fmaxf(c[j][2], c[j][3]));
    }
    mx0 = fmaxf(mx0, __shfl_xor_sync(0xffffffffu, mx0, 1));
    mx0 = fmaxf(mx0, __shfl_xor_sync(0xffffffffu, mx0, 2));
    mx1 = fmaxf(mx1, __shfl_xor_sync(0xffffffffu, mx1, 1));
    mx1 = fmaxf(mx1, __shfl_xor_sync(0xffffffffu, mx1, 2));
    float sum0 = 0.f, sum1 = 0.f;
    #pragma unroll
    for (int j = 0; j < 8; j++) {
        c[j][0] = __expf(c[j][0] - mx0);
        c[j][1] = __expf(c[j][1] - mx0);
        c[j][2] = __expf(c[j][2] - mx1);
        c[j][3] = __expf(c[j][3] - mx1);
        sum0 += c[j][0] + c[j][1];
        sum1 += c[j][2] + c[j][3];
    }
    sum0 += __shfl_xor_sync(0xffffffffu, sum0, 1);
    sum0 += __shfl_xor_sync(0xffffffffu, sum0, 2);
    sum1 += __shfl_xor_sync(0xffffffffu, sum1, 1);
    sum1 += __shfl_xor_sync(0xffffffffu, sum1, 2);

    float co[4][4];
    #pragma unroll
    for (int j = 0; j < 4; j++)
        #pragma unroll
        for (int q = 0; q < 4; q++) co[j][q] = 0.f;

    #pragma unroll
    for (int t = 0; t < 4; t++) {
        uint32_t a[4];
        a[0] = pack_h2(c[2 * t][0],     c[2 * t][1]);
        a[1] = pack_h2(c[2 * t][2],     c[2 * t][3]);
        a[2] = pack_h2(c[2 * t + 1][0], c[2 * t + 1][1]);
        a[3] = pack_h2(c[2 * t + 1][2], c[2 * t + 1][3]);
        #pragma unroll
        for (int p = 0; p < 2; p++) {
            uint32_t r0, r1, r2, r3;
            ldm_x4t(r0, r1, r2, r3,
                    (uint32_t)__cvta_generic_to_shared(&vs[t * 16 + lrow][p * 16 + lsel * 8]));
            uint32_t b0[2] = {r0, r1}, b1[2] = {r2, r3};
            mma_f16(co[2 * p],     a, b0);
            mma_f16(co[2 * p + 1], a, b1);
        }
    }

    const float rinv0 = 1.f / sum0, rinv1 = 1.f / sum1;
    const int row0 = wm + lr, row1 = row0 + 8;
    bf16* ob = out + (size_t)w * 49 * CH + hh * 32;
    #pragma unroll
    for (int nt = 0; nt < 4; nt++) {
        int col = nt * 8 + 2 * lk;
        if (row0 < 49)
            *(bf162*)&ob[(size_t)row0 * CH + col] =
                __floats2bfloat162_rn(co[nt][0] * rinv0, co[nt][1] * rinv0);
        if (row1 < 49)
            *(bf162*)&ob[(size_t)row1 * CH + col] =
                __floats2bfloat162_rn(co[nt][2] * rinv1, co[nt][3] * rinv1);
    }
}

// ---------------- driver ----------------
extern "C" void kernel_launch(void* const* d_in, const int* in_sizes, int n_in,
                              void* d_out, int out_size) {
    const float* x      = (const float*)d_in[0];
    const float* n1g    = (const float*)d_in[1];
    const float* n1b    = (const float*)d_in[2];
    const float* qkv_w  = (const float*)d_in[3];
    const float* qkv_b  = (const float*)d_in[4];
    const float* relb   = (const float*)d_in[5];
    const float* proj_w = (const float*)d_in[6];
    const float* proj_b = (const float*)d_in[7];
    const float* n2g    = (const float*)d_in[8];
    const float* n2b    = (const float*)d_in[9];
    const float* fc1_w  = (const float*)d_in[10];
    const float* fc1_b  = (const float*)d_in[11];
    const float* fc2_w  = (const float*)d_in[12];
    const float* fc2_b  = (const float*)d_in[13];
    float* out = (float*)d_out;

    bf16 *xw, *qkv, *z, *m1, *wq, *wp, *w1, *w2;
    float *y;
    cudaGetSymbolAddress((void**)&xw,  g_xw);
    cudaGetSymbolAddress((void**)&qkv, g_qkv);
    cudaGetSymbolAddress((void**)&y,   g_y);
    cudaGetSymbolAddress((void**)&z,   g_z);
    cudaGetSymbolAddress((void**)&m1,  g_m1);
    cudaGetSymbolAddress((void**)&wq,  g_wq);
    cudaGetSymbolAddress((void**)&wp,  g_wp);
    cudaGetSymbolAddress((void**)&w1,  g_w1);
    cudaGetSymbolAddress((void**)&w2,  g_w2);

    static bool attr_set = false;
    if (!attr_set) {
        cudaFuncSetAttribute(mma_gemm<0>, cudaFuncAttributeMaxDynamicSharedMemorySize, SMEM_GEMM);
        cudaFuncSetAttribute(mma_gemm<2>, cudaFuncAttributeMaxDynamicSharedMemorySize, SMEM_GEMM);
        cudaFuncSetAttribute(mma_gemm<3>, cudaFuncAttributeMaxDynamicSharedMemorySize, SMEM_GEMM);
        cudaFuncSetAttribute(proj_ln_gemm, cudaFuncAttributeMaxDynamicSharedMemorySize, SMEM_PROJ);
        attr_set = true;
    }

    const int MROWS = T_TOK / 256;  // 392

    conv_all<<<(NW0 + NW1 + NW2 + NW3) / 512, 256>>>(qkv_w, proj_w, fc1_w, fc2_w, wq, wp, w1, w2);

    ln1_kernel<<<T_TOK / 8, 256>>>(x, n1g, n1b, xw);
    mma_gemm<0><<<dim3(768 / 128, MROWS), 256, SMEM_GEMM>>>(xw, wq, qkv_b, (float*)qkv, 768, 256, nullptr);
    attn_kernel<<<2048 * HEADS, 128>>>(qkv, relb, xw);
    proj_ln_gemm<<<T_TOK / 128, 256, SMEM_PROJ>>>(xw, wp, proj_b, x, y, n2g, n2b, z);
    mma_gemm<2><<<dim3(1024 / 128, MROWS), 256, SMEM_GEMM>>>(z, w1, fc1_b, (float*)m1, 1024, 256, nullptr);
    mma_gemm<3><<<dim3(256 / 128, MROWS), 256, SMEM_GEMM>>>(m1, w2, fc2_b, out, 256, 1024, y);
}